// round 9
// baseline (speedup 1.0000x reference)
#include <cuda_runtime.h>
#include <cuda_bf16.h>
#include <math.h>

// ----------------------------------------------------------------------------
// SpectralLoss on GB300 — register radix-8 FFT (R6 structure) + MUFU twiddles.
// K1: T-mean (scalar loads, direct to regs) + row-pair FFT + Hermitian split.
// K2: column FFT (4 cols/block) + weighted radial binning -> coalesced partials.
// K3: per-bin reduce; last arriving block computes the loss scalar.
// ----------------------------------------------------------------------------

#define N512 512
#define NB   16
#define NT   8
#define RS   264                  // g_fft row stride (float2)
#define K2_BLOCKS (NB * 65)       // 1040
#define FPAD(i) ((i) + (((i) >> 6) << 3))   // +8 pad per 64 slots

__device__ float2 g_fft[(size_t)NB * N512 * RS];     // ~17.3 MB
__device__ float  g_part[K2_BLOCKS * 256];           // [block][bin]
__device__ float  g_cnt [65 * 256];                  // [group][bin]
__device__ float  g_seg2[256];
__device__ float  g_cnt2[256];
__device__ unsigned g_arrive;

__device__ __forceinline__ float2 cadd(float2 a, float2 b){ return make_float2(a.x+b.x, a.y+b.y); }
__device__ __forceinline__ float2 csub(float2 a, float2 b){ return make_float2(a.x-b.x, a.y-b.y); }
__device__ __forceinline__ float2 cmul(float2 a, float2 b){
    return make_float2(a.x*b.x - a.y*b.y, a.x*b.y + a.y*b.x);
}
__device__ __forceinline__ float2 mul_mi(float2 a){ return make_float2(a.y, -a.x); }
__device__ __forceinline__ float2 mul_w81(float2 a){
    const float C = 0.70710678118654752f;
    return make_float2(C*(a.x+a.y), C*(a.y-a.x));
}
__device__ __forceinline__ float2 mul_w83(float2 a){
    const float C = 0.70710678118654752f;
    return make_float2(C*(a.y-a.x), -C*(a.x+a.y));
}

__device__ __forceinline__ void dft8(const float2* a, float2* X){
    float2 t0 = cadd(a[0], a[4]), t1 = cadd(a[1], a[5]);
    float2 t2 = cadd(a[2], a[6]), t3 = cadd(a[3], a[7]);
    float2 u0 = csub(a[0], a[4]);
    float2 u1 = mul_w81(csub(a[1], a[5]));
    float2 u2 = mul_mi (csub(a[2], a[6]));
    float2 u3 = mul_w83(csub(a[3], a[7]));
    float2 s0 = cadd(t0, t2), s1 = cadd(t1, t3);
    float2 d0 = csub(t0, t2), d1 = mul_mi(csub(t1, t3));
    float2 e0 = cadd(u0, u2), e1 = cadd(u1, u3);
    float2 f0 = csub(u0, u2), f1 = mul_mi(csub(u1, u3));
    X[0] = cadd(s0, s1); X[4] = csub(s0, s1);
    X[2] = cadd(d0, d1); X[6] = csub(d0, d1);
    X[1] = cadd(e0, e1); X[5] = csub(e0, e1);
    X[3] = cadd(f0, f1); X[7] = csub(f0, f1);
}

// log-depth powers w^1..w^7 of a unit complex w
__device__ __forceinline__ void cpowers(float2 w1, float2* W){
    float2 w2 = cmul(w1, w1);
    float2 w4 = cmul(w2, w2);
    W[1] = w1; W[2] = w2; W[4] = w4;
    W[3] = cmul(w2, w1);
    W[5] = cmul(w4, w1);
    W[6] = cmul(w4, w2);
    W[7] = cmul(w4, W[3]);
}

// stage 1: a[p] = x[t + 64p] -> y_q[t] stored at 72q+t
__device__ __forceinline__ void fft_stage1(const float2* a, int t, float* sre, float* sim){
    float2 b[8];
    dft8(a, b);
    float ang = -6.2831853071795864f * (float)t / 512.0f;
    float2 w1; __sincosf(ang, &w1.y, &w1.x);
    float2 W[8]; cpowers(w1, W);
    sre[t] = b[0].x; sim[t] = b[0].y;
#pragma unroll
    for (int q = 1; q < 8; q++){
        float2 c = cmul(b[q], W[q]);
        sre[72*q + t] = c.x; sim[72*q + t] = c.y;
    }
}

// stages 2+3: consumes y in shared, returns X[w] at ky = ky0 + 64w
__device__ __forceinline__ void fft_stage23(float* sre, float* sim, int t,
                                            float2* X, int* ky0_out){
    const int q = t >> 3, u = t & 7;
    float2 a[8], b[8];
#pragma unroll
    for (int v = 0; v < 8; v++){
        int idx = 72*q + u + 8*v;
        a[v] = make_float2(sre[idx], sim[idx]);
    }
    dft8(a, b);
    float ang = -6.2831853071795864f * (float)u / 64.0f;
    float2 w1; __sincosf(ang, &w1.y, &w1.x);
    float2 W[8]; cpowers(w1, W);
    __syncwarp();
    {   // r = 0
        int idx = 72*q + (u ^ ((2*q) & 7));
        sre[idx] = b[0].x; sim[idx] = b[0].y;
    }
#pragma unroll
    for (int r = 1; r < 8; r++){
        float2 c = cmul(b[r], W[r]);
        int swz = (2*q + (r >> 2)) & 7;
        int idx = 72*q + 8*r + (u ^ swz);
        sre[idx] = c.x; sim[idx] = c.y;
    }
    __syncwarp();
    const int r3 = u;
    const int swz = (2*q + (r3 >> 2)) & 7;
#pragma unroll
    for (int uu = 0; uu < 8; uu++){
        int idx = 72*q + 8*r3 + (uu ^ swz);
        a[uu] = make_float2(sre[idx], sim[idx]);
    }
    dft8(a, X);
    *ky0_out = q + 8*r3;
}

// ---------------- K1: T-mean + packed row-pair FFT + Hermitian split ---------
__global__ __launch_bounds__(256) void k_mean_rowfft(const float* __restrict__ in){
    __shared__ float sre[4][584], sim[4][584];
    const int tid  = threadIdx.x;
    const int team = tid >> 6;
    const int t    = tid & 63;
    const int b    = blockIdx.x >> 6;
    const int hp   = ((blockIdx.x & 63) << 2) + team;    // row pair 0..255

    const float* base = in + ((size_t)b * NT * N512 + 2 * hp) * N512;
    float2 a[8];
#pragma unroll
    for (int p = 0; p < 8; p++) a[p] = make_float2(0.f, 0.f);
#pragma unroll
    for (int tt = 0; tt < NT; tt++){
        const float* pe = base + (size_t)tt * (N512 * N512);
#pragma unroll
        for (int p = 0; p < 8; p++){
            a[p].x += pe[t + 64*p];            // even row -> re
            a[p].y += pe[N512 + t + 64*p];     // odd row  -> im
        }
    }
#pragma unroll
    for (int p = 0; p < 8; p++){ a[p].x *= 0.125f; a[p].y *= 0.125f; }

    fft_stage1(a, t, sre[team], sim[team]);
    __syncthreads();
    float2 X[8]; int ky0;
    fft_stage23(sre[team], sim[team], t, X, &ky0);
    __syncthreads();
#pragma unroll
    for (int w = 0; w < 8; w++){
        sre[team][ky0 + 72*w] = X[w].x;        // = FPAD(ky0 + 64w)
        sim[team][ky0 + 72*w] = X[w].y;
    }
    __syncthreads();

    // Hermitian split: Z = Fe + i*Fo
    float2* oute = g_fft + ((size_t)b * N512 + 2 * hp) * RS;
    float2* outo = oute + RS;
    for (int k = t; k <= 256; k += 64){
        int m = (N512 - k) & (N512 - 1);
        float2 zk = make_float2(sre[team][FPAD(k)], sim[team][FPAD(k)]);
        float2 zm = make_float2(sre[team][FPAD(m)], sim[team][FPAD(m)]);
        oute[k] = make_float2(0.5f*(zk.x + zm.x), 0.5f*(zk.y - zm.y));
        outo[k] = make_float2(0.5f*(zk.y + zm.y), 0.5f*(zm.x - zk.x));
    }
}

// ---------------- K2: column FFT (4 cols/block) + radial binning -------------
__global__ __launch_bounds__(256) void k_colfft_bin(){
    __shared__ float sre[4][584], sim[4][584];
    __shared__ float pb[256], pc[256];
    const int tid = threadIdx.x;
    const int b   = blockIdx.x / 65;
    const int g   = blockIdx.x % 65;
    const int kx0 = g << 2;

    pb[tid] = 0.f; pc[tid] = 0.f;

    const float2* src = g_fft + (size_t)b * (N512 * RS);
#pragma unroll
    for (int k = 0; k < 8; k++){
        int idx = tid + (k << 8);
        int row = idx >> 2, c = idx & 3;
        int kx  = kx0 + c;
        float2 v = (kx <= 256) ? src[(size_t)row * RS + kx] : make_float2(0.f, 0.f);
        sre[c][FPAD(row)] = v.x; sim[c][FPAD(row)] = v.y;
    }
    __syncthreads();

    const int team = tid >> 6, t = tid & 63;
    float2 a[8];
#pragma unroll
    for (int p = 0; p < 8; p++)
        a[p] = make_float2(sre[team][t + 72*p], sim[team][t + 72*p]);  // FPAD(t+64p)
    fft_stage1(a, t, sre[team], sim[team]);
    __syncthreads();
    float2 X[8]; int ky0;
    fft_stage23(sre[team], sim[team], t, X, &ky0);

    const int kx = kx0 + team;
    if (kx <= 256){
        float wgt = (kx == 0 || kx == 256) ? 1.f : 2.f;   // mirror column folded in
        int   dx  = kx - 256;
        float fdx2 = (float)(dx * dx);
        const bool cblk = (b == 0);
#pragma unroll
        for (int w = 0; w < 8; w++){
            int   ky = ky0 + (w << 6);
            float p  = wgt * (X[w].x * X[w].x + X[w].y * X[w].y);
            int   dy = ky - 256;
            int   rr = (int)__fsqrt_rn((float)(dy * dy) + fdx2);
            if (rr < 256){
                atomicAdd(&pb[rr], p);
                if (cblk) atomicAdd(&pc[rr], wgt);
            }
        }
    }
    __syncthreads();
    g_part[blockIdx.x * 256 + tid] = pb[tid];       // coalesced 1KB per block
    if (b == 0) g_cnt[g * 256 + tid] = pc[tid];
}

// ------- K3: per-bin reduce + last-block loss -------
__global__ __launch_bounds__(256) void k_reduce_final(float* __restrict__ out){
    __shared__ float red[256];
    __shared__ int   s_last;
    __shared__ float s_gs, s_rs;
    const int bin = blockIdx.x, tid = threadIdx.x;

    float s = 0.f;
    for (int blk = tid; blk < K2_BLOCKS; blk += 256)
        s += g_part[blk * 256 + bin];
    red[tid] = s; __syncthreads();
    for (int o = 128; o > 0; o >>= 1){ if (tid < o) red[tid] += red[tid + o]; __syncthreads(); }
    float segv = red[0];
    __syncthreads();

    red[tid] = (tid < 65) ? g_cnt[tid * 256 + bin] : 0.f;
    __syncthreads();
    for (int o = 128; o > 0; o >>= 1){ if (tid < o) red[tid] += red[tid + o]; __syncthreads(); }

    if (tid == 0){
        g_seg2[bin] = segv;
        g_cnt2[bin] = red[0];
        __threadfence();
        unsigned old = atomicAdd(&g_arrive, 1u);
        s_last = (old == 255u) ? 1 : 0;
    }
    __syncthreads();
    if (!s_last) return;
    if (tid == 0) g_arrive = 0;

    volatile float* vseg = g_seg2;
    volatile float* vcnt = g_cnt2;
    float gen = 0.f, refv = 0.f;
    if (tid >= 1){
        float cr    = vcnt[tid];
        float denom = fmaxf(cr, 1.0f) * (float)NB;
        gen  = (cr > 0.f) ? vseg[tid] / denom : 0.0f;
        refv = powf((float)tid, -5.0f / 3.0f);
    }

    red[tid] = gen; __syncthreads();
    for (int o = 128; o > 0; o >>= 1){ if (tid < o) red[tid] += red[tid + o]; __syncthreads(); }
    if (tid == 0) s_gs = red[0] + 1e-8f;
    __syncthreads();
    red[tid] = refv; __syncthreads();
    for (int o = 128; o > 0; o >>= 1){ if (tid < o) red[tid] += red[tid + o]; __syncthreads(); }
    if (tid == 0) s_rs = red[0] + 1e-8f;
    __syncthreads();

    float d = (tid >= 1) ? (gen / s_gs - refv / s_rs) : 0.f;
    red[tid] = d * d; __syncthreads();
    for (int o = 128; o > 0; o >>= 1){ if (tid < o) red[tid] += red[tid + o]; __syncthreads(); }
    if (tid == 0) out[0] = red[0] / 255.0f;
}

extern "C" void kernel_launch(void* const* d_in, const int* in_sizes, int n_in,
                              void* d_out, int out_size) {
    (void)in_sizes; (void)n_in; (void)out_size;
    const float* in  = (const float*)d_in[0];
    float*       out = (float*)d_out;

    k_mean_rowfft<<<NB * 64, 256>>>(in);
    k_colfft_bin<<<K2_BLOCKS, 256>>>();
    k_reduce_final<<<256, 256>>>(out);
}

// round 10
// speedup vs baseline: 1.0006x; 1.0006x over previous
#include <cuda_runtime.h>
#include <cuda_bf16.h>
#include <math.h>

// ----------------------------------------------------------------------------
// SpectralLoss on GB300 — register radix-8 FFT + run-accumulated radial binning.
// K1: T-mean + packed row-pair FFT + Hermitian split -> g_fft[k=0..256].
// K2: column FFT (4 cols/block); X written back to shared tile; each thread
//     bins 8 CONSECUTIVE ky via run-accumulation (near-conflict-free atomics).
// K3: per-bin reduce; last arriving block computes the loss scalar.
// ----------------------------------------------------------------------------

#define N512 512
#define NB   16
#define NT   8
#define RS   264                  // g_fft row stride (float2)
#define K2_BLOCKS (NB * 65)       // 1040
#define FPAD(i) ((i) + (((i) >> 6) << 3))   // +8 pad per 64 slots

__device__ float2 g_fft[(size_t)NB * N512 * RS];     // ~17.3 MB
__device__ float  g_part[K2_BLOCKS * 256];           // [block][bin]
__device__ float  g_cnt [65 * 256];                  // [group][bin]
__device__ float  g_seg2[256];
__device__ float  g_cnt2[256];
__device__ unsigned g_arrive;

__device__ __forceinline__ float2 cadd(float2 a, float2 b){ return make_float2(a.x+b.x, a.y+b.y); }
__device__ __forceinline__ float2 csub(float2 a, float2 b){ return make_float2(a.x-b.x, a.y-b.y); }
__device__ __forceinline__ float2 cmul(float2 a, float2 b){
    return make_float2(a.x*b.x - a.y*b.y, a.x*b.y + a.y*b.x);
}
__device__ __forceinline__ float2 mul_mi(float2 a){ return make_float2(a.y, -a.x); }
__device__ __forceinline__ float2 mul_w81(float2 a){
    const float C = 0.70710678118654752f;
    return make_float2(C*(a.x+a.y), C*(a.y-a.x));
}
__device__ __forceinline__ float2 mul_w83(float2 a){
    const float C = 0.70710678118654752f;
    return make_float2(C*(a.y-a.x), -C*(a.x+a.y));
}

__device__ __forceinline__ void dft8(const float2* a, float2* X){
    float2 t0 = cadd(a[0], a[4]), t1 = cadd(a[1], a[5]);
    float2 t2 = cadd(a[2], a[6]), t3 = cadd(a[3], a[7]);
    float2 u0 = csub(a[0], a[4]);
    float2 u1 = mul_w81(csub(a[1], a[5]));
    float2 u2 = mul_mi (csub(a[2], a[6]));
    float2 u3 = mul_w83(csub(a[3], a[7]));
    float2 s0 = cadd(t0, t2), s1 = cadd(t1, t3);
    float2 d0 = csub(t0, t2), d1 = mul_mi(csub(t1, t3));
    float2 e0 = cadd(u0, u2), e1 = cadd(u1, u3);
    float2 f0 = csub(u0, u2), f1 = mul_mi(csub(u1, u3));
    X[0] = cadd(s0, s1); X[4] = csub(s0, s1);
    X[2] = cadd(d0, d1); X[6] = csub(d0, d1);
    X[1] = cadd(e0, e1); X[5] = csub(e0, e1);
    X[3] = cadd(f0, f1); X[7] = csub(f0, f1);
}

// stage 1: a[p] = x[t + 64p] -> y_q[t] stored at 72q+t
__device__ __forceinline__ void fft_stage1(const float2* a, int t, float* sre, float* sim){
    float2 b[8];
    dft8(a, b);
    float ang = -6.2831853071795864f * (float)t / 512.0f;
    float2 w1; sincosf(ang, &w1.y, &w1.x);
    sre[t] = b[0].x; sim[t] = b[0].y;
    float2 wp = w1;
#pragma unroll
    for (int q = 1; q < 8; q++){
        float2 c = cmul(b[q], wp);
        sre[72*q + t] = c.x; sim[72*q + t] = c.y;
        wp = cmul(wp, w1);
    }
}

// stages 2+3: consumes y in shared, returns X[w] at ky = ky0 + 64w
__device__ __forceinline__ void fft_stage23(float* sre, float* sim, int t,
                                            float2* X, int* ky0_out){
    const int q = t >> 3, u = t & 7;
    float2 a[8], b[8];
#pragma unroll
    for (int v = 0; v < 8; v++){
        int idx = 72*q + u + 8*v;
        a[v] = make_float2(sre[idx], sim[idx]);
    }
    dft8(a, b);
    float ang = -6.2831853071795864f * (float)u / 64.0f;
    float2 w1; sincosf(ang, &w1.y, &w1.x);
    __syncwarp();
    {   // r = 0
        int idx = 72*q + (u ^ ((2*q) & 7));
        sre[idx] = b[0].x; sim[idx] = b[0].y;
    }
    float2 wp = w1;
#pragma unroll
    for (int r = 1; r < 8; r++){
        float2 c = cmul(b[r], wp);
        int swz = (2*q + (r >> 2)) & 7;
        int idx = 72*q + 8*r + (u ^ swz);
        sre[idx] = c.x; sim[idx] = c.y;
        wp = cmul(wp, w1);
    }
    __syncwarp();
    const int r3 = u;
    const int swz = (2*q + (r3 >> 2)) & 7;
#pragma unroll
    for (int uu = 0; uu < 8; uu++){
        int idx = 72*q + 8*r3 + (uu ^ swz);
        a[uu] = make_float2(sre[idx], sim[idx]);
    }
    dft8(a, X);
    *ky0_out = q + 8*r3;
}

// ---------------- K1: T-mean + packed row-pair FFT + Hermitian split ---------
__global__ __launch_bounds__(256) void k_mean_rowfft(const float* __restrict__ in){
    __shared__ float sre[4][584], sim[4][584];
    const int tid  = threadIdx.x;
    const int team = tid >> 6;
    const int t    = tid & 63;
    const int b    = blockIdx.x >> 6;
    const int hp   = ((blockIdx.x & 63) << 2) + team;    // row pair 0..255

    const float* base = in + ((size_t)b * NT * N512 + 2 * hp) * N512;
    float2 a[8];
#pragma unroll
    for (int p = 0; p < 8; p++) a[p] = make_float2(0.f, 0.f);
#pragma unroll
    for (int tt = 0; tt < NT; tt++){
        const float* pe = base + (size_t)tt * (N512 * N512);
#pragma unroll
        for (int p = 0; p < 8; p++){
            a[p].x += pe[t + 64*p];            // even row -> re
            a[p].y += pe[N512 + t + 64*p];     // odd row  -> im
        }
    }
#pragma unroll
    for (int p = 0; p < 8; p++){ a[p].x *= 0.125f; a[p].y *= 0.125f; }

    fft_stage1(a, t, sre[team], sim[team]);
    __syncthreads();
    float2 X[8]; int ky0;
    fft_stage23(sre[team], sim[team], t, X, &ky0);
    __syncthreads();
#pragma unroll
    for (int w = 0; w < 8; w++){
        sre[team][ky0 + 72*w] = X[w].x;        // = FPAD(ky0 + 64w)
        sim[team][ky0 + 72*w] = X[w].y;
    }
    __syncthreads();

    // Hermitian split: Z = Fe + i*Fo
    float2* oute = g_fft + ((size_t)b * N512 + 2 * hp) * RS;
    float2* outo = oute + RS;
    for (int k = t; k <= 256; k += 64){
        int m = (N512 - k) & (N512 - 1);
        float2 zk = make_float2(sre[team][FPAD(k)], sim[team][FPAD(k)]);
        float2 zm = make_float2(sre[team][FPAD(m)], sim[team][FPAD(m)]);
        oute[k] = make_float2(0.5f*(zk.x + zm.x), 0.5f*(zk.y - zm.y));
        outo[k] = make_float2(0.5f*(zk.y + zm.y), 0.5f*(zm.x - zk.x));
    }
}

// ---------------- K2: column FFT (4 cols/block) + run-accumulated binning ----
__global__ __launch_bounds__(256) void k_colfft_bin(){
    __shared__ float sre[4][584], sim[4][584];
    __shared__ float pb[256], pc[256];
    const int tid = threadIdx.x;
    const int b   = blockIdx.x / 65;
    const int g   = blockIdx.x % 65;
    const int kx0 = g << 2;

    pb[tid] = 0.f; pc[tid] = 0.f;

    const float2* src = g_fft + (size_t)b * (N512 * RS);
#pragma unroll
    for (int k = 0; k < 8; k++){
        int idx = tid + (k << 8);
        int row = idx >> 2, c = idx & 3;
        int kx  = kx0 + c;
        float2 v = (kx <= 256) ? src[(size_t)row * RS + kx] : make_float2(0.f, 0.f);
        sre[c][FPAD(row)] = v.x; sim[c][FPAD(row)] = v.y;
    }
    __syncthreads();

    const int team = tid >> 6, t = tid & 63;
    float2 a[8];
#pragma unroll
    for (int p = 0; p < 8; p++)
        a[p] = make_float2(sre[team][t + 72*p], sim[team][t + 72*p]);  // FPAD(t+64p)
    fft_stage1(a, t, sre[team], sim[team]);
    __syncthreads();
    float2 X[8]; int ky0;
    fft_stage23(sre[team], sim[team], t, X, &ky0);
    __syncthreads();
    // write spectrum back to tile so binning can walk consecutive ky
#pragma unroll
    for (int w = 0; w < 8; w++){
        sre[team][ky0 + 72*w] = X[w].x;        // = FPAD(ky0 + 64w)
        sim[team][ky0 + 72*w] = X[w].y;
    }
    __syncthreads();

    // binning: thread owns 8 consecutive ky of its column; same-bin neighbors
    // collapse into register runs -> one atomic per run, conflict degree <= 2.
    const int kx = kx0 + team;
    if (kx <= 256){
        const float wgt = (kx == 0 || kx == 256) ? 1.f : 2.f;
        const int   dx  = kx - 256;
        const float fdx2 = (float)(dx * dx);
        const bool  cblk = (b == 0);
        const int   kyb  = t << 3;             // 8*t .. 8*t+7
        int   cur  = -1;
        float accp = 0.f, accc = 0.f;
#pragma unroll
        for (int k = 0; k < 8; k++){
            int   ky = kyb + k;
            float vx = sre[team][FPAD(ky)];
            float vy = sim[team][FPAD(ky)];
            float p  = wgt * (vx * vx + vy * vy);
            int   dy = ky - 256;
            int   rr = (int)__fsqrt_rn((float)(dy * dy) + fdx2);
            if (rr == cur){ accp += p; accc += wgt; }
            else {
                if (cur >= 0 && cur < 256){
                    atomicAdd(&pb[cur], accp);
                    if (cblk) atomicAdd(&pc[cur], accc);
                }
                cur = rr; accp = p; accc = wgt;
            }
        }
        if (cur >= 0 && cur < 256){
            atomicAdd(&pb[cur], accp);
            if (cblk) atomicAdd(&pc[cur], accc);
        }
    }
    __syncthreads();
    g_part[blockIdx.x * 256 + tid] = pb[tid];       // coalesced 1KB per block
    if (b == 0) g_cnt[g * 256 + tid] = pc[tid];
}

// ------- K3: per-bin reduce + last-block loss -------
__global__ __launch_bounds__(256) void k_reduce_final(float* __restrict__ out){
    __shared__ float red[256];
    __shared__ int   s_last;
    __shared__ float s_gs, s_rs;
    const int bin = blockIdx.x, tid = threadIdx.x;

    float s = 0.f;
    for (int blk = tid; blk < K2_BLOCKS; blk += 256)
        s += g_part[blk * 256 + bin];
    red[tid] = s; __syncthreads();
    for (int o = 128; o > 0; o >>= 1){ if (tid < o) red[tid] += red[tid + o]; __syncthreads(); }
    float segv = red[0];
    __syncthreads();

    red[tid] = (tid < 65) ? g_cnt[tid * 256 + bin] : 0.f;
    __syncthreads();
    for (int o = 128; o > 0; o >>= 1){ if (tid < o) red[tid] += red[tid + o]; __syncthreads(); }

    if (tid == 0){
        g_seg2[bin] = segv;
        g_cnt2[bin] = red[0];
        __threadfence();
        unsigned old = atomicAdd(&g_arrive, 1u);
        s_last = (old == 255u) ? 1 : 0;
    }
    __syncthreads();
    if (!s_last) return;
    if (tid == 0) g_arrive = 0;

    volatile float* vseg = g_seg2;
    volatile float* vcnt = g_cnt2;
    float gen = 0.f, refv = 0.f;
    if (tid >= 1){
        float cr    = vcnt[tid];
        float denom = fmaxf(cr, 1.0f) * (float)NB;
        gen  = (cr > 0.f) ? vseg[tid] / denom : 0.0f;
        refv = powf((float)tid, -5.0f / 3.0f);
    }

    red[tid] = gen; __syncthreads();
    for (int o = 128; o > 0; o >>= 1){ if (tid < o) red[tid] += red[tid + o]; __syncthreads(); }
    if (tid == 0) s_gs = red[0] + 1e-8f;
    __syncthreads();
    red[tid] = refv; __syncthreads();
    for (int o = 128; o > 0; o >>= 1){ if (tid < o) red[tid] += red[tid + o]; __syncthreads(); }
    if (tid == 0) s_rs = red[0] + 1e-8f;
    __syncthreads();

    float d = (tid >= 1) ? (gen / s_gs - refv / s_rs) : 0.f;
    red[tid] = d * d; __syncthreads();
    for (int o = 128; o > 0; o >>= 1){ if (tid < o) red[tid] += red[tid + o]; __syncthreads(); }
    if (tid == 0) out[0] = red[0] / 255.0f;
}

extern "C" void kernel_launch(void* const* d_in, const int* in_sizes, int n_in,
                              void* d_out, int out_size) {
    (void)in_sizes; (void)n_in; (void)out_size;
    const float* in  = (const float*)d_in[0];
    float*       out = (float*)d_out;

    k_mean_rowfft<<<NB * 64, 256>>>(in);
    k_colfft_bin<<<K2_BLOCKS, 256>>>();
    k_reduce_final<<<256, 256>>>(out);
}

// round 11
// speedup vs baseline: 1.0075x; 1.0069x over previous
#include <cuda_runtime.h>
#include <cuda_bf16.h>
#include <math.h>

// ----------------------------------------------------------------------------
// SpectralLoss on GB300 — register radix-8 FFT + precomputed twiddle tables.
// K0: fill twiddle tables (accurate sincosf), 1 tiny block.
// K1: T-mean + packed row-pair FFT + Hermitian split -> g_fft[k=0..256].
// K2: column FFT (4 cols/block) + weighted radial binning -> coalesced partials.
// K3: per-bin reduce; last arriving block computes the loss scalar.
// ----------------------------------------------------------------------------

#define N512 512
#define NB   16
#define NT   8
#define RS   264                  // g_fft row stride (float2)
#define K2_BLOCKS (NB * 65)       // 1040
#define FPAD(i) ((i) + (((i) >> 6) << 3))   // +8 pad per 64 slots

__device__ float2 g_fft[(size_t)NB * N512 * RS];     // ~17.3 MB
__device__ float  g_part[K2_BLOCKS * 256];           // [block][bin]
__device__ float  g_cnt [65 * 256];                  // [group][bin]
__device__ float  g_seg2[256];
__device__ float  g_cnt2[256];
__device__ unsigned g_arrive;
__device__ float2 g_tw1[7 * 64];                     // W512^{t*q}, q=1..7
__device__ float2 g_tw2[8 * 7];                      // W64^{u*r},  r=1..7

__device__ __forceinline__ float2 cadd(float2 a, float2 b){ return make_float2(a.x+b.x, a.y+b.y); }
__device__ __forceinline__ float2 csub(float2 a, float2 b){ return make_float2(a.x-b.x, a.y-b.y); }
__device__ __forceinline__ float2 cmul(float2 a, float2 b){
    return make_float2(a.x*b.x - a.y*b.y, a.x*b.y + a.y*b.x);
}
__device__ __forceinline__ float2 mul_mi(float2 a){ return make_float2(a.y, -a.x); }
__device__ __forceinline__ float2 mul_w81(float2 a){
    const float C = 0.70710678118654752f;
    return make_float2(C*(a.x+a.y), C*(a.y-a.x));
}
__device__ __forceinline__ float2 mul_w83(float2 a){
    const float C = 0.70710678118654752f;
    return make_float2(C*(a.y-a.x), -C*(a.x+a.y));
}

__device__ __forceinline__ void dft8(const float2* a, float2* X){
    float2 t0 = cadd(a[0], a[4]), t1 = cadd(a[1], a[5]);
    float2 t2 = cadd(a[2], a[6]), t3 = cadd(a[3], a[7]);
    float2 u0 = csub(a[0], a[4]);
    float2 u1 = mul_w81(csub(a[1], a[5]));
    float2 u2 = mul_mi (csub(a[2], a[6]));
    float2 u3 = mul_w83(csub(a[3], a[7]));
    float2 s0 = cadd(t0, t2), s1 = cadd(t1, t3);
    float2 d0 = csub(t0, t2), d1 = mul_mi(csub(t1, t3));
    float2 e0 = cadd(u0, u2), e1 = cadd(u1, u3);
    float2 f0 = csub(u0, u2), f1 = mul_mi(csub(u1, u3));
    X[0] = cadd(s0, s1); X[4] = csub(s0, s1);
    X[2] = cadd(d0, d1); X[6] = csub(d0, d1);
    X[1] = cadd(e0, e1); X[5] = csub(e0, e1);
    X[3] = cadd(f0, f1); X[7] = csub(f0, f1);
}

// ---------------- K0: twiddle tables ----------------
__global__ void k_twiddle_init(){
    const int i = threadIdx.x;
    if (i < 448){
        int q = (i >> 6) + 1, t = i & 63;
        float ang = -6.2831853071795864f * (float)(t * q) / 512.0f;
        float s, c; sincosf(ang, &s, &c);
        g_tw1[i] = make_float2(c, s);
    }
    if (i < 56){
        int u = i / 7, r = (i % 7) + 1;
        float ang = -6.2831853071795864f * (float)(u * r) / 64.0f;
        float s, c; sincosf(ang, &s, &c);
        g_tw2[i] = make_float2(c, s);
    }
}

// stage 1: a[p] = x[t + 64p] -> y_q[t] stored at 72q+t  (twiddles from g_tw1)
__device__ __forceinline__ void fft_stage1(const float2* a, int t, float* sre, float* sim){
    float2 W[8];
#pragma unroll
    for (int q = 1; q < 8; q++) W[q] = g_tw1[((q - 1) << 6) + t];   // coalesced LDG.64
    float2 b[8];
    dft8(a, b);
    sre[t] = b[0].x; sim[t] = b[0].y;
#pragma unroll
    for (int q = 1; q < 8; q++){
        float2 c = cmul(b[q], W[q]);
        sre[72*q + t] = c.x; sim[72*q + t] = c.y;
    }
}

// stages 2+3: consumes y in shared, returns X[w] at ky = ky0 + 64w
__device__ __forceinline__ void fft_stage23(float* sre, float* sim, int t,
                                            float2* X, int* ky0_out){
    const int q = t >> 3, u = t & 7;
    float2 W[8];
#pragma unroll
    for (int r = 1; r < 8; r++) W[r] = g_tw2[u * 7 + (r - 1)];      // L1-resident
    float2 a[8], b[8];
#pragma unroll
    for (int v = 0; v < 8; v++){
        int idx = 72*q + u + 8*v;
        a[v] = make_float2(sre[idx], sim[idx]);
    }
    dft8(a, b);
    __syncwarp();
    {   // r = 0
        int idx = 72*q + (u ^ ((2*q) & 7));
        sre[idx] = b[0].x; sim[idx] = b[0].y;
    }
#pragma unroll
    for (int r = 1; r < 8; r++){
        float2 c = cmul(b[r], W[r]);
        int swz = (2*q + (r >> 2)) & 7;
        int idx = 72*q + 8*r + (u ^ swz);
        sre[idx] = c.x; sim[idx] = c.y;
    }
    __syncwarp();
    const int r3 = u;
    const int swz = (2*q + (r3 >> 2)) & 7;
#pragma unroll
    for (int uu = 0; uu < 8; uu++){
        int idx = 72*q + 8*r3 + (uu ^ swz);
        a[uu] = make_float2(sre[idx], sim[idx]);
    }
    dft8(a, X);
    *ky0_out = q + 8*r3;
}

// ---------------- K1: T-mean + packed row-pair FFT + Hermitian split ---------
__global__ __launch_bounds__(256) void k_mean_rowfft(const float* __restrict__ in){
    __shared__ float sre[4][584], sim[4][584];
    const int tid  = threadIdx.x;
    const int team = tid >> 6;
    const int t    = tid & 63;
    const int b    = blockIdx.x >> 6;
    const int hp   = ((blockIdx.x & 63) << 2) + team;    // row pair 0..255

    const float* base = in + ((size_t)b * NT * N512 + 2 * hp) * N512;
    float2 a[8];
#pragma unroll
    for (int p = 0; p < 8; p++) a[p] = make_float2(0.f, 0.f);
#pragma unroll
    for (int tt = 0; tt < NT; tt++){
        const float* pe = base + (size_t)tt * (N512 * N512);
#pragma unroll
        for (int p = 0; p < 8; p++){
            a[p].x += pe[t + 64*p];            // even row -> re
            a[p].y += pe[N512 + t + 64*p];     // odd row  -> im
        }
    }
#pragma unroll
    for (int p = 0; p < 8; p++){ a[p].x *= 0.125f; a[p].y *= 0.125f; }

    fft_stage1(a, t, sre[team], sim[team]);
    __syncthreads();
    float2 X[8]; int ky0;
    fft_stage23(sre[team], sim[team], t, X, &ky0);
    __syncthreads();
#pragma unroll
    for (int w = 0; w < 8; w++){
        sre[team][ky0 + 72*w] = X[w].x;        // = FPAD(ky0 + 64w)
        sim[team][ky0 + 72*w] = X[w].y;
    }
    __syncthreads();

    // Hermitian split: Z = Fe + i*Fo
    float2* oute = g_fft + ((size_t)b * N512 + 2 * hp) * RS;
    float2* outo = oute + RS;
    for (int k = t; k <= 256; k += 64){
        int m = (N512 - k) & (N512 - 1);
        float2 zk = make_float2(sre[team][FPAD(k)], sim[team][FPAD(k)]);
        float2 zm = make_float2(sre[team][FPAD(m)], sim[team][FPAD(m)]);
        oute[k] = make_float2(0.5f*(zk.x + zm.x), 0.5f*(zk.y - zm.y));
        outo[k] = make_float2(0.5f*(zk.y + zm.y), 0.5f*(zm.x - zk.x));
    }
}

// ---------------- K2: column FFT (4 cols/block) + radial binning -------------
__global__ __launch_bounds__(256) void k_colfft_bin(){
    __shared__ float sre[4][584], sim[4][584];
    __shared__ float pb[256], pc[256];
    const int tid = threadIdx.x;
    const int b   = blockIdx.x / 65;
    const int g   = blockIdx.x % 65;
    const int kx0 = g << 2;

    pb[tid] = 0.f; pc[tid] = 0.f;

    const float2* src = g_fft + (size_t)b * (N512 * RS);
#pragma unroll
    for (int k = 0; k < 8; k++){
        int idx = tid + (k << 8);
        int row = idx >> 2, c = idx & 3;
        int kx  = kx0 + c;
        float2 v = (kx <= 256) ? src[(size_t)row * RS + kx] : make_float2(0.f, 0.f);
        sre[c][FPAD(row)] = v.x; sim[c][FPAD(row)] = v.y;
    }
    __syncthreads();

    const int team = tid >> 6, t = tid & 63;
    float2 a[8];
#pragma unroll
    for (int p = 0; p < 8; p++)
        a[p] = make_float2(sre[team][t + 72*p], sim[team][t + 72*p]);  // FPAD(t+64p)
    fft_stage1(a, t, sre[team], sim[team]);
    __syncthreads();
    float2 X[8]; int ky0;
    fft_stage23(sre[team], sim[team], t, X, &ky0);

    const int kx = kx0 + team;
    if (kx <= 256){
        float wgt = (kx == 0 || kx == 256) ? 1.f : 2.f;   // mirror column folded in
        int   dx  = kx - 256;
        float fdx2 = (float)(dx * dx);
        const bool cblk = (b == 0);
#pragma unroll
        for (int w = 0; w < 8; w++){
            int   ky = ky0 + (w << 6);
            float p  = wgt * (X[w].x * X[w].x + X[w].y * X[w].y);
            int   dy = ky - 256;
            int   rr = (int)__fsqrt_rn((float)(dy * dy) + fdx2);
            if (rr < 256){
                atomicAdd(&pb[rr], p);
                if (cblk) atomicAdd(&pc[rr], wgt);
            }
        }
    }
    __syncthreads();
    g_part[blockIdx.x * 256 + tid] = pb[tid];       // coalesced 1KB per block
    if (b == 0) g_cnt[g * 256 + tid] = pc[tid];
}

// ------- K3: per-bin reduce + last-block loss -------
__global__ __launch_bounds__(256) void k_reduce_final(float* __restrict__ out){
    __shared__ float red[256];
    __shared__ int   s_last;
    __shared__ float s_gs, s_rs;
    const int bin = blockIdx.x, tid = threadIdx.x;

    float s = 0.f;
    for (int blk = tid; blk < K2_BLOCKS; blk += 256)
        s += g_part[blk * 256 + bin];
    red[tid] = s; __syncthreads();
    for (int o = 128; o > 0; o >>= 1){ if (tid < o) red[tid] += red[tid + o]; __syncthreads(); }
    float segv = red[0];
    __syncthreads();

    red[tid] = (tid < 65) ? g_cnt[tid * 256 + bin] : 0.f;
    __syncthreads();
    for (int o = 128; o > 0; o >>= 1){ if (tid < o) red[tid] += red[tid + o]; __syncthreads(); }

    if (tid == 0){
        g_seg2[bin] = segv;
        g_cnt2[bin] = red[0];
        __threadfence();
        unsigned old = atomicAdd(&g_arrive, 1u);
        s_last = (old == 255u) ? 1 : 0;
    }
    __syncthreads();
    if (!s_last) return;
    if (tid == 0) g_arrive = 0;

    volatile float* vseg = g_seg2;
    volatile float* vcnt = g_cnt2;
    float gen = 0.f, refv = 0.f;
    if (tid >= 1){
        float cr    = vcnt[tid];
        float denom = fmaxf(cr, 1.0f) * (float)NB;
        gen  = (cr > 0.f) ? vseg[tid] / denom : 0.0f;
        refv = powf((float)tid, -5.0f / 3.0f);
    }

    red[tid] = gen; __syncthreads();
    for (int o = 128; o > 0; o >>= 1){ if (tid < o) red[tid] += red[tid + o]; __syncthreads(); }
    if (tid == 0) s_gs = red[0] + 1e-8f;
    __syncthreads();
    red[tid] = refv; __syncthreads();
    for (int o = 128; o > 0; o >>= 1){ if (tid < o) red[tid] += red[tid + o]; __syncthreads(); }
    if (tid == 0) s_rs = red[0] + 1e-8f;
    __syncthreads();

    float d = (tid >= 1) ? (gen / s_gs - refv / s_rs) : 0.f;
    red[tid] = d * d; __syncthreads();
    for (int o = 128; o > 0; o >>= 1){ if (tid < o) red[tid] += red[tid + o]; __syncthreads(); }
    if (tid == 0) out[0] = red[0] / 255.0f;
}

extern "C" void kernel_launch(void* const* d_in, const int* in_sizes, int n_in,
                              void* d_out, int out_size) {
    (void)in_sizes; (void)n_in; (void)out_size;
    const float* in  = (const float*)d_in[0];
    float*       out = (float*)d_out;

    k_twiddle_init<<<1, 512>>>();
    k_mean_rowfft<<<NB * 64, 256>>>(in);
    k_colfft_bin<<<K2_BLOCKS, 256>>>();
    k_reduce_final<<<256, 256>>>(out);
}

// round 12
// speedup vs baseline: 1.0381x; 1.0304x over previous
#include <cuda_runtime.h>
#include <cuda_bf16.h>
#include <math.h>

// ----------------------------------------------------------------------------
// SpectralLoss on GB300 — register radix-8 FFT + twiddle tables + 2-level tail.
// K0: fill twiddle tables (accurate sincosf), 1 tiny block.
// K1: T-mean + packed row-pair FFT + Hermitian split -> g_fft[k=0..256].
// K2: column FFT (4 cols/block) + weighted radial binning -> coalesced partials.
// K3: 65 blocks; each coalesced-sums 16 partial rows; last arriving block
//     does the coalesced level-2 sum + loss scalar.
// ----------------------------------------------------------------------------

#define N512 512
#define NB   16
#define NT   8
#define RS   264                  // g_fft row stride (float2)
#define K2_BLOCKS (NB * 65)       // 1040
#define FPAD(i) ((i) + (((i) >> 6) << 3))   // +8 pad per 64 slots

__device__ float2 g_fft[(size_t)NB * N512 * RS];     // ~17.3 MB
__device__ float  g_part [K2_BLOCKS * 256];          // [block][bin]
__device__ float  g_part2[65 * 256];                 // level-1 sums [blk][bin]
__device__ float  g_cnt  [65 * 256];                 // [group][bin]
__device__ unsigned g_arrive;
__device__ float2 g_tw1[7 * 64];                     // W512^{t*q}, q=1..7
__device__ float2 g_tw2[8 * 7];                      // W64^{u*r},  r=1..7

__device__ __forceinline__ float2 cadd(float2 a, float2 b){ return make_float2(a.x+b.x, a.y+b.y); }
__device__ __forceinline__ float2 csub(float2 a, float2 b){ return make_float2(a.x-b.x, a.y-b.y); }
__device__ __forceinline__ float2 cmul(float2 a, float2 b){
    return make_float2(a.x*b.x - a.y*b.y, a.x*b.y + a.y*b.x);
}
__device__ __forceinline__ float2 mul_mi(float2 a){ return make_float2(a.y, -a.x); }
__device__ __forceinline__ float2 mul_w81(float2 a){
    const float C = 0.70710678118654752f;
    return make_float2(C*(a.x+a.y), C*(a.y-a.x));
}
__device__ __forceinline__ float2 mul_w83(float2 a){
    const float C = 0.70710678118654752f;
    return make_float2(C*(a.y-a.x), -C*(a.x+a.y));
}

__device__ __forceinline__ void dft8(const float2* a, float2* X){
    float2 t0 = cadd(a[0], a[4]), t1 = cadd(a[1], a[5]);
    float2 t2 = cadd(a[2], a[6]), t3 = cadd(a[3], a[7]);
    float2 u0 = csub(a[0], a[4]);
    float2 u1 = mul_w81(csub(a[1], a[5]));
    float2 u2 = mul_mi (csub(a[2], a[6]));
    float2 u3 = mul_w83(csub(a[3], a[7]));
    float2 s0 = cadd(t0, t2), s1 = cadd(t1, t3);
    float2 d0 = csub(t0, t2), d1 = mul_mi(csub(t1, t3));
    float2 e0 = cadd(u0, u2), e1 = cadd(u1, u3);
    float2 f0 = csub(u0, u2), f1 = mul_mi(csub(u1, u3));
    X[0] = cadd(s0, s1); X[4] = csub(s0, s1);
    X[2] = cadd(d0, d1); X[6] = csub(d0, d1);
    X[1] = cadd(e0, e1); X[5] = csub(e0, e1);
    X[3] = cadd(f0, f1); X[7] = csub(f0, f1);
}

// ---------------- K0: twiddle tables ----------------
__global__ void k_twiddle_init(){
    const int i = threadIdx.x;
    if (i < 448){
        int q = (i >> 6) + 1, t = i & 63;
        float ang = -6.2831853071795864f * (float)(t * q) / 512.0f;
        float s, c; sincosf(ang, &s, &c);
        g_tw1[i] = make_float2(c, s);
    }
    if (i < 56){
        int u = i / 7, r = (i % 7) + 1;
        float ang = -6.2831853071795864f * (float)(u * r) / 64.0f;
        float s, c; sincosf(ang, &s, &c);
        g_tw2[i] = make_float2(c, s);
    }
}

// stage 1: a[p] = x[t + 64p] -> y_q[t] stored at 72q+t  (twiddles from g_tw1)
__device__ __forceinline__ void fft_stage1(const float2* a, int t, float* sre, float* sim){
    float2 W[8];
#pragma unroll
    for (int q = 1; q < 8; q++) W[q] = g_tw1[((q - 1) << 6) + t];   // coalesced LDG.64
    float2 b[8];
    dft8(a, b);
    sre[t] = b[0].x; sim[t] = b[0].y;
#pragma unroll
    for (int q = 1; q < 8; q++){
        float2 c = cmul(b[q], W[q]);
        sre[72*q + t] = c.x; sim[72*q + t] = c.y;
    }
}

// stages 2+3: consumes y in shared, returns X[w] at ky = ky0 + 64w
__device__ __forceinline__ void fft_stage23(float* sre, float* sim, int t,
                                            float2* X, int* ky0_out){
    const int q = t >> 3, u = t & 7;
    float2 W[8];
#pragma unroll
    for (int r = 1; r < 8; r++) W[r] = g_tw2[u * 7 + (r - 1)];      // L1-resident
    float2 a[8], b[8];
#pragma unroll
    for (int v = 0; v < 8; v++){
        int idx = 72*q + u + 8*v;
        a[v] = make_float2(sre[idx], sim[idx]);
    }
    dft8(a, b);
    __syncwarp();
    {   // r = 0
        int idx = 72*q + (u ^ ((2*q) & 7));
        sre[idx] = b[0].x; sim[idx] = b[0].y;
    }
#pragma unroll
    for (int r = 1; r < 8; r++){
        float2 c = cmul(b[r], W[r]);
        int swz = (2*q + (r >> 2)) & 7;
        int idx = 72*q + 8*r + (u ^ swz);
        sre[idx] = c.x; sim[idx] = c.y;
    }
    __syncwarp();
    const int r3 = u;
    const int swz = (2*q + (r3 >> 2)) & 7;
#pragma unroll
    for (int uu = 0; uu < 8; uu++){
        int idx = 72*q + 8*r3 + (uu ^ swz);
        a[uu] = make_float2(sre[idx], sim[idx]);
    }
    dft8(a, X);
    *ky0_out = q + 8*r3;
}

// ---------------- K1: T-mean + packed row-pair FFT + Hermitian split ---------
__global__ __launch_bounds__(256) void k_mean_rowfft(const float* __restrict__ in){
    __shared__ float sre[4][584], sim[4][584];
    const int tid  = threadIdx.x;
    const int team = tid >> 6;
    const int t    = tid & 63;
    const int b    = blockIdx.x >> 6;
    const int hp   = ((blockIdx.x & 63) << 2) + team;    // row pair 0..255

    const float* base = in + ((size_t)b * NT * N512 + 2 * hp) * N512;
    float2 a[8];
#pragma unroll
    for (int p = 0; p < 8; p++) a[p] = make_float2(0.f, 0.f);
#pragma unroll
    for (int tt = 0; tt < NT; tt++){
        const float* pe = base + (size_t)tt * (N512 * N512);
#pragma unroll
        for (int p = 0; p < 8; p++){
            a[p].x += pe[t + 64*p];            // even row -> re
            a[p].y += pe[N512 + t + 64*p];     // odd row  -> im
        }
    }
#pragma unroll
    for (int p = 0; p < 8; p++){ a[p].x *= 0.125f; a[p].y *= 0.125f; }

    fft_stage1(a, t, sre[team], sim[team]);
    __syncthreads();
    float2 X[8]; int ky0;
    fft_stage23(sre[team], sim[team], t, X, &ky0);
    __syncthreads();
#pragma unroll
    for (int w = 0; w < 8; w++){
        sre[team][ky0 + 72*w] = X[w].x;        // = FPAD(ky0 + 64w)
        sim[team][ky0 + 72*w] = X[w].y;
    }
    __syncthreads();

    // Hermitian split: Z = Fe + i*Fo
    float2* oute = g_fft + ((size_t)b * N512 + 2 * hp) * RS;
    float2* outo = oute + RS;
    for (int k = t; k <= 256; k += 64){
        int m = (N512 - k) & (N512 - 1);
        float2 zk = make_float2(sre[team][FPAD(k)], sim[team][FPAD(k)]);
        float2 zm = make_float2(sre[team][FPAD(m)], sim[team][FPAD(m)]);
        oute[k] = make_float2(0.5f*(zk.x + zm.x), 0.5f*(zk.y - zm.y));
        outo[k] = make_float2(0.5f*(zk.y + zm.y), 0.5f*(zm.x - zk.x));
    }
}

// ---------------- K2: column FFT (4 cols/block) + radial binning -------------
__global__ __launch_bounds__(256) void k_colfft_bin(){
    __shared__ float sre[4][584], sim[4][584];
    __shared__ float pb[256], pc[256];
    const int tid = threadIdx.x;
    const int b   = blockIdx.x / 65;
    const int g   = blockIdx.x % 65;
    const int kx0 = g << 2;

    pb[tid] = 0.f; pc[tid] = 0.f;

    const float2* src = g_fft + (size_t)b * (N512 * RS);
#pragma unroll
    for (int k = 0; k < 8; k++){
        int idx = tid + (k << 8);
        int row = idx >> 2, c = idx & 3;
        int kx  = kx0 + c;
        float2 v = (kx <= 256) ? src[(size_t)row * RS + kx] : make_float2(0.f, 0.f);
        sre[c][FPAD(row)] = v.x; sim[c][FPAD(row)] = v.y;
    }
    __syncthreads();

    const int team = tid >> 6, t = tid & 63;
    float2 a[8];
#pragma unroll
    for (int p = 0; p < 8; p++)
        a[p] = make_float2(sre[team][t + 72*p], sim[team][t + 72*p]);  // FPAD(t+64p)
    fft_stage1(a, t, sre[team], sim[team]);
    __syncthreads();
    float2 X[8]; int ky0;
    fft_stage23(sre[team], sim[team], t, X, &ky0);

    const int kx = kx0 + team;
    if (kx <= 256){
        float wgt = (kx == 0 || kx == 256) ? 1.f : 2.f;   // mirror column folded in
        int   dx  = kx - 256;
        float fdx2 = (float)(dx * dx);
        const bool cblk = (b == 0);
#pragma unroll
        for (int w = 0; w < 8; w++){
            int   ky = ky0 + (w << 6);
            float p  = wgt * (X[w].x * X[w].x + X[w].y * X[w].y);
            int   dy = ky - 256;
            int   rr = (int)__fsqrt_rn((float)(dy * dy) + fdx2);
            if (rr < 256){
                atomicAdd(&pb[rr], p);
                if (cblk) atomicAdd(&pc[rr], wgt);
            }
        }
    }
    __syncthreads();
    g_part[blockIdx.x * 256 + tid] = pb[tid];       // coalesced 1KB per block
    if (b == 0) g_cnt[g * 256 + tid] = pc[tid];
}

// ------- K3: 2-level coalesced reduce + last-block loss -------
__global__ __launch_bounds__(256) void k_reduce_final(float* __restrict__ out){
    __shared__ float red[256];
    __shared__ int   s_last;
    __shared__ float s_gs, s_rs;
    const int bid = blockIdx.x, tid = threadIdx.x;

    // level 1: sum 16 contiguous partial rows (fully coalesced, MLP=16)
    float s = 0.f;
#pragma unroll
    for (int r = 0; r < 16; r++)
        s += g_part[(bid * 16 + r) * 256 + tid];
    g_part2[bid * 256 + tid] = s;
    __threadfence();
    if (tid == 0){
        unsigned old = atomicAdd(&g_arrive, 1u);
        s_last = (old == 64u) ? 1 : 0;
    }
    __syncthreads();
    if (!s_last) return;
    if (tid == 0) g_arrive = 0;          // reset for next graph replay

    // level 2: coalesced rows of g_part2 / g_cnt
    volatile float* vp2 = g_part2;
    volatile float* vct = g_cnt;
    float seg = 0.f, cnt = 0.f;
    for (int i = 0; i < 65; i++){
        seg += vp2[i * 256 + tid];
        cnt += vct[i * 256 + tid];
    }

    // loss (bin r = tid, valid 1..255)
    float gen = 0.f, refv = 0.f;
    if (tid >= 1){
        float denom = fmaxf(cnt, 1.0f) * (float)NB;
        gen  = (cnt > 0.f) ? seg / denom : 0.0f;
        refv = powf((float)tid, -5.0f / 3.0f);
    }

    red[tid] = gen; __syncthreads();
    for (int o = 128; o > 0; o >>= 1){ if (tid < o) red[tid] += red[tid + o]; __syncthreads(); }
    if (tid == 0) s_gs = red[0] + 1e-8f;
    __syncthreads();
    red[tid] = refv; __syncthreads();
    for (int o = 128; o > 0; o >>= 1){ if (tid < o) red[tid] += red[tid + o]; __syncthreads(); }
    if (tid == 0) s_rs = red[0] + 1e-8f;
    __syncthreads();

    float d = (tid >= 1) ? (gen / s_gs - refv / s_rs) : 0.f;
    red[tid] = d * d; __syncthreads();
    for (int o = 128; o > 0; o >>= 1){ if (tid < o) red[tid] += red[tid + o]; __syncthreads(); }
    if (tid == 0) out[0] = red[0] / 255.0f;
}

extern "C" void kernel_launch(void* const* d_in, const int* in_sizes, int n_in,
                              void* d_out, int out_size) {
    (void)in_sizes; (void)n_in; (void)out_size;
    const float* in  = (const float*)d_in[0];
    float*       out = (float*)d_out;

    k_twiddle_init<<<1, 512>>>();
    k_mean_rowfft<<<NB * 64, 256>>>(in);
    k_colfft_bin<<<K2_BLOCKS, 256>>>();
    k_reduce_final<<<65, 256>>>(out);
}